// round 4
// baseline (speedup 1.0000x reference)
#include <cuda_runtime.h>
#include <cuda_bf16.h>
#include <math.h>
#include <stdint.h>

#define H 1024
#define V 32000
#define L 4096
#define NCH 24            // K chunks: 8 (Ah*Bh) + 8 (Ah*Bl) + 8 (Al*Bh), each K=128

// ---------------- device scratch ----------------
__device__ int8_t g_A[(size_t)L * 2048];   // [Ah(1024) | Al(1024)] per row, 8 MB
__device__ int8_t g_B[(size_t)H * 2048];   // [Bh(1024) | Bl(1024)] per row, 2 MB
__device__ float g_sA[L];                  // rowmax/127
__device__ float g_sB[H];                  // rowmax/(127*256)
__device__ float g_scores[L];
__device__ float g_q[H];
__device__ float g_attn[L];
__device__ float g_context[H];
__device__ float g_x[H];
__device__ float g_gi[3 * H];
__device__ float g_gh[3 * H];
__device__ float g_ov[H];

// ---------------- helpers ----------------
__device__ __forceinline__ uint32_t smem_u32(const void* p) {
    uint32_t a;
    asm("{ .reg .u64 t; cvta.to.shared.u64 t, %1; cvt.u32.u64 %0, t; }" : "=r"(a) : "l"(p));
    return a;
}
__device__ __forceinline__ uint32_t sw(uint32_t off) {   // Swizzle<3,4,3> on 128B rows
    return off ^ ((off >> 3) & 0x70u);
}
#define CP_ASYNC16(dst, src) \
    asm volatile("cp.async.cg.shared.global [%0], [%1], 16;" :: "r"(dst), "l"(src) : "memory")
#define CP_COMMIT() asm volatile("cp.async.commit_group;" ::: "memory")
#define CP_WAIT(n)  asm volatile("cp.async.wait_group %0;" :: "n"(n) : "memory")
#define LDSM_X4(r, a) \
    asm volatile("ldmatrix.sync.aligned.m8n8.x4.shared.b16 {%0,%1,%2,%3}, [%4];" \
                 : "=r"((r)[0]), "=r"((r)[1]), "=r"((r)[2]), "=r"((r)[3]) : "r"(a))

__device__ __forceinline__ void mma_s8(int* c, const uint32_t* a, uint32_t b0, uint32_t b1) {
    asm volatile("mma.sync.aligned.m16n8k32.row.col.s32.s8.s8.s32 "
                 "{%0,%1,%2,%3}, {%4,%5,%6,%7}, {%8,%9}, {%0,%1,%2,%3};"
                 : "+r"(c[0]), "+r"(c[1]), "+r"(c[2]), "+r"(c[3])
                 : "r"(a[0]), "r"(a[1]), "r"(a[2]), "r"(a[3]), "r"(b0), "r"(b1));
}

__device__ __forceinline__ float warp_sum(float v) {
#pragma unroll
    for (int o = 16; o; o >>= 1) v += __shfl_xor_sync(0xffffffffu, v, o);
    return v;
}
__device__ __forceinline__ float warp_max(float v) {
#pragma unroll
    for (int o = 16; o; o >>= 1) v = fmaxf(v, __shfl_xor_sync(0xffffffffu, v, o));
    return v;
}

// ---------------- fused prologue: quantize enc & uW rows, k1 GEMV, zero accum ----------------
// block roles: [0,4096) enc row quant (+zero g_scores[b]);
//              [4096,5120) uW row quant (+zero g_context[b-4096]);
//              [5120,5248) k1: q = wW@h0 + wb + ub (8 rows/block)
__device__ __forceinline__ void quant_row(const float* __restrict__ src, int8_t* dst,
                                          float* scale_out, float scale_mul, float* red) {
    int tid = threadIdx.x;
    const float4* s4 = (const float4*)src;
    float4 v = s4[tid];
    float m = fmaxf(fmaxf(fabsf(v.x), fabsf(v.y)), fmaxf(fabsf(v.z), fabsf(v.w)));
    m = warp_max(m);
    if ((tid & 31) == 0) red[tid >> 5] = m;
    __syncthreads();
    float rm = fmaxf(fmaxf(fmaxf(red[0], red[1]), fmaxf(red[2], red[3])),
                     fmaxf(fmaxf(red[4], red[5]), fmaxf(red[6], red[7])));
    rm = fmaxf(rm, 1e-20f);
    float c = 127.0f / rm;
    float xs[4] = {v.x * c, v.y * c, v.z * c, v.w * c};
    char hi[4], lo[4];
#pragma unroll
    for (int j = 0; j < 4; j++) {
        float ah = rintf(xs[j]);
        float resid = xs[j] - ah;
        float al = rintf(resid * 256.0f);
        al = fminf(fmaxf(al, -127.0f), 127.0f);
        hi[j] = (char)(int)ah;
        lo[j] = (char)(int)al;
    }
    *(char4*)(dst + tid * 4) = make_char4(hi[0], hi[1], hi[2], hi[3]);
    *(char4*)(dst + 1024 + tid * 4) = make_char4(lo[0], lo[1], lo[2], lo[3]);
    if (tid == 0) *scale_out = rm * scale_mul;
}

__global__ void __launch_bounds__(256) k_prologue(const float* __restrict__ enc,
                                                  const float* __restrict__ uW,
                                                  const float* __restrict__ h0,
                                                  const float* __restrict__ wW,
                                                  const float* __restrict__ wb,
                                                  const float* __restrict__ ub) {
    __shared__ float red[8];
    int b = blockIdx.x;
    if (b < L) {
        if (threadIdx.x == 0) g_scores[b] = 0.f;
        quant_row(enc + (size_t)b * H, g_A + (size_t)b * 2048, &g_sA[b], 1.0f / 127.0f, red);
    } else if (b < L + H) {
        int r = b - L;
        if (threadIdx.x == 0) g_context[r] = 0.f;
        quant_row(uW + (size_t)r * H, g_B + (size_t)r * 2048, &g_sB[r], 1.0f / (127.0f * 256.0f), red);
    } else {
        int warp = ((b - L - H) << 3) + (threadIdx.x >> 5);
        int lane = threadIdx.x & 31;
        const float4* row = (const float4*)(wW + (size_t)warp * H);
        const float4* h4 = (const float4*)h0;
        float s = 0.f;
#pragma unroll
        for (int i = 0; i < 8; i++) {
            float4 a = row[lane + 32 * i];
            float4 hh = h4[lane + 32 * i];
            s += a.x * hh.x + a.y * hh.y + a.z * hh.z + a.w * hh.w;
        }
        s = warp_sum(s);
        if (lane == 0) g_q[warp] = s + wb[warp] + ub[warp];
    }
}

// ---------------- K2: int8 IMMA scores GEMM ----------------
// pre[l,n] = (256*sum AhBh + sum AhBl + sum AlBh) * sA[l] * sB[n]
// g_scores[l] += sum_n vW[n]*tanh(q[n] + pre[l,n])
// 128x128 tile, chunk K=128 s8 (128B rows), cp.async double buffer, 8 warps 4x2.
#define SMEM_DYN (2 * 32768 + 1024)

__global__ void __launch_bounds__(256, 2) k2_scores(const float* __restrict__ vW) {
    extern __shared__ char dsm[];
    __shared__ float sq[128], sv[128], ssb[128], sred[128][2];

    uint32_t sbase = (smem_u32(dsm) + 1023u) & ~1023u;
    int tid = threadIdx.x, wid = tid >> 5, lane = tid & 31;
    int wm = wid & 3, wn = wid >> 2;
    int bm = blockIdx.x * 128, bn = blockIdx.y * 128;

    if (tid < 128) {
        sq[tid] = g_q[bn + tid];
        sv[tid] = vW[bn + tid];
        ssb[tid] = g_sB[bn + tid];
    }

    const int8_t* gA = g_A + (size_t)bm * 2048;
    const int8_t* gB = g_B + (size_t)bn * 2048;

    int lr[4], lc[4];
    uint32_t loff[4];
#pragma unroll
    for (int i = 0; i < 4; i++) {
        int idx = tid + 256 * i;
        lr[i] = idx >> 3;
        lc[i] = idx & 7;
        loff[i] = sw((uint32_t)(lr[i] * 128 + lc[i] * 16));
    }

#define LOAD_CHUNK(c, buf) do { \
    uint32_t ao_ = ((c) < 8) ? (uint32_t)(c) * 128u : ((c) < 16) ? (uint32_t)((c) - 8) * 128u : 1024u + (uint32_t)((c) - 16) * 128u; \
    uint32_t bo_ = ((c) < 8) ? (uint32_t)(c) * 128u : ((c) < 16) ? 1024u + (uint32_t)((c) - 8) * 128u : (uint32_t)((c) - 16) * 128u; \
    uint32_t s_ = sbase + (buf) * 32768u; \
    _Pragma("unroll") \
    for (int i_ = 0; i_ < 4; i_++) { \
        const int8_t* a_ = gA + (size_t)lr[i_] * 2048 + ao_ + lc[i_] * 16; \
        const int8_t* b_ = gB + (size_t)lr[i_] * 2048 + bo_ + lc[i_] * 16; \
        CP_ASYNC16(s_ + loff[i_], a_); \
        CP_ASYNC16(s_ + 16384u + loff[i_], b_); \
    } \
    CP_COMMIT(); \
} while (0)

    int acc[2][8][4] = {};

    LOAD_CHUNK(0, 0);

    uint32_t aRow[2], bRow[4];
#pragma unroll
    for (int mt = 0; mt < 2; mt++)
        aRow[mt] = (uint32_t)((wm * 32 + mt * 16 + (lane & 15)) * 128 + (lane >> 4) * 16);
#pragma unroll
    for (int bp = 0; bp < 4; bp++)
        bRow[bp] = (uint32_t)((wn * 64 + bp * 16 + (lane & 15)) * 128 + (lane >> 4) * 16);

    for (int c = 0; c < NCH; c++) {
        if (c + 1 < NCH) {
            LOAD_CHUNK(c + 1, (c + 1) & 1);
            CP_WAIT(1);
        } else {
            CP_WAIT(0);
        }
        __syncthreads();
        // after all Ah*Bh chunks, scale accumulators by 256 so cross terms add at 1/256 weight
        if (c == 8) {
#pragma unroll
            for (int mt = 0; mt < 2; mt++)
#pragma unroll
                for (int nt = 0; nt < 8; nt++)
#pragma unroll
                    for (int j = 0; j < 4; j++) acc[mt][nt][j] <<= 8;
        }
        uint32_t sA = sbase + (uint32_t)(c & 1) * 32768u;
        uint32_t sB = sA + 16384u;
#pragma unroll
        for (int ks = 0; ks < 4; ks++) {
            uint32_t afr[2][4];
#pragma unroll
            for (int mt = 0; mt < 2; mt++)
                LDSM_X4(afr[mt], sA + sw(aRow[mt] + ks * 32));
            uint32_t bfr[4][4];
#pragma unroll
            for (int bp = 0; bp < 4; bp++)
                LDSM_X4(bfr[bp], sB + sw(bRow[bp] + ks * 32));
#pragma unroll
            for (int mt = 0; mt < 2; mt++)
#pragma unroll
                for (int nt = 0; nt < 8; nt++) {
                    uint32_t b0 = bfr[nt >> 1][nt & 1];
                    uint32_t b1 = bfr[nt >> 1][(nt & 1) + 2];
                    mma_s8(acc[mt][nt], afr[mt], b0, b1);
                }
        }
        __syncthreads();
    }

    // ---- epilogue: pre = acc * sA[l] * sB[n]; weighted tanh row reduction ----
    int cb = wn * 64;
    int c0 = 2 * (lane & 3);
    float p[2][2];
#pragma unroll
    for (int mt = 0; mt < 2; mt++)
#pragma unroll
        for (int half = 0; half < 2; half++) {
            float sa = g_sA[bm + wm * 32 + mt * 16 + half * 8 + (lane >> 2)];
            float s = 0.f;
#pragma unroll
            for (int nt = 0; nt < 8; nt++) {
#pragma unroll
                for (int j = 0; j < 2; j++) {
                    int n = cb + nt * 8 + c0 + j;
                    float pre = (float)acc[mt][nt][half * 2 + j] * sa * ssb[n];
                    s += sv[n] * tanhf(sq[n] + pre);
                }
            }
            p[mt][half] = s;
        }
#pragma unroll
    for (int mt = 0; mt < 2; mt++)
#pragma unroll
        for (int half = 0; half < 2; half++) {
            float s = p[mt][half];
            s += __shfl_xor_sync(0xffffffffu, s, 1);
            s += __shfl_xor_sync(0xffffffffu, s, 2);
            p[mt][half] = s;
        }
    if ((lane & 3) == 0) {
#pragma unroll
        for (int mt = 0; mt < 2; mt++)
#pragma unroll
            for (int half = 0; half < 2; half++)
                sred[wm * 32 + mt * 16 + half * 8 + (lane >> 2)][wn] = p[mt][half];
    }
    __syncthreads();
    if (tid < 128)
        atomicAdd(&g_scores[bm + tid], sred[tid][0] + sred[tid][1]);
}

// ---------------- K3: softmax ----------------
__global__ void k3_softmax(float* __restrict__ out_attn) {
    __shared__ float sm[32];
    int t = threadIdx.x;
    float v[4];
    float mx = -1e30f;
#pragma unroll
    for (int i = 0; i < 4; i++) {
        v[i] = g_scores[t + 1024 * i];
        mx = fmaxf(mx, v[i]);
    }
    mx = warp_max(mx);
    if ((t & 31) == 0) sm[t >> 5] = mx;
    __syncthreads();
    if (t < 32) {
        float m2 = sm[t];
        m2 = warp_max(m2);
        if (t == 0) sm[0] = m2;
    }
    __syncthreads();
    mx = sm[0];
    __syncthreads();
    float se = 0.f;
#pragma unroll
    for (int i = 0; i < 4; i++) {
        v[i] = expf(v[i] - mx);
        se += v[i];
    }
    se = warp_sum(se);
    if ((t & 31) == 0) sm[t >> 5] = se;
    __syncthreads();
    if (t < 32) {
        float s2 = sm[t];
        s2 = warp_sum(s2);
        if (t == 0) sm[0] = s2;
    }
    __syncthreads();
    float inv = 1.f / sm[0];
#pragma unroll
    for (int i = 0; i < 4; i++) {
        float a = v[i] * inv;
        g_attn[t + 1024 * i] = a;
        out_attn[t + 1024 * i] = a;
    }
}

// ---------------- K4: context = attn^T @ enc ----------------
__global__ void k4_context(const float* __restrict__ enc) {
    __shared__ float aw[64];
    int t = threadIdx.x;
    int l0 = blockIdx.x * 64;
    if (t < 64) aw[t] = g_attn[l0 + t];
    __syncthreads();
    float s = 0.f;
#pragma unroll 8
    for (int l = 0; l < 64; l++) s += aw[l] * enc[(size_t)(l0 + l) * H + t];
    atomicAdd(&g_context[t], s);
}

// ---------------- K5: x = relu(cW @ [context;embedded] + cb) ----------------
__global__ void k5_combine(const float* __restrict__ cW, const float* __restrict__ cb,
                           const float* __restrict__ emb, const int* __restrict__ tok) {
    int warp = (blockIdx.x * blockDim.x + threadIdx.x) >> 5;
    int lane = threadIdx.x & 31;
    if (warp >= H) return;
    const float4* r1 = (const float4*)(cW + (size_t)warp * 2 * H);
    const float4* r2 = r1 + H / 4;
    const float4* c4 = (const float4*)g_context;
    const float4* e4 = (const float4*)(emb + (size_t)tok[0] * H);
    float s = 0.f;
#pragma unroll
    for (int i = 0; i < 8; i++) {
        float4 a = r1[lane + 32 * i];
        float4 b = c4[lane + 32 * i];
        s += a.x * b.x + a.y * b.y + a.z * b.z + a.w * b.w;
        float4 a2 = r2[lane + 32 * i];
        float4 b2 = e4[lane + 32 * i];
        s += a2.x * b2.x + a2.y * b2.y + a2.z * b2.z + a2.w * b2.w;
    }
    s = warp_sum(s);
    if (lane == 0) g_x[warp] = fmaxf(s + cb[warp], 0.f);
}

// ---------------- K6: GRU gate GEMVs ----------------
__global__ void k6_gru_gemv(const float* __restrict__ w_ih, const float* __restrict__ b_ih,
                            const float* __restrict__ w_hh, const float* __restrict__ b_hh,
                            const float* __restrict__ hprev) {
    int warp = (blockIdx.x * blockDim.x + threadIdx.x) >> 5;
    int lane = threadIdx.x & 31;
    if (warp >= 6 * H) return;
    const float4* row;
    const float4* vec;
    float bias;
    float* out;
    int idx;
    if (warp < 3 * H) {
        idx = warp;
        row = (const float4*)(w_ih + (size_t)idx * H);
        vec = (const float4*)g_x;
        bias = b_ih[idx];
        out = g_gi;
    } else {
        idx = warp - 3 * H;
        row = (const float4*)(w_hh + (size_t)idx * H);
        vec = (const float4*)hprev;
        bias = b_hh[idx];
        out = g_gh;
    }
    float s = 0.f;
#pragma unroll
    for (int i = 0; i < 8; i++) {
        float4 a = row[lane + 32 * i];
        float4 b = vec[lane + 32 * i];
        s += a.x * b.x + a.y * b.y + a.z * b.z + a.w * b.w;
    }
    s = warp_sum(s);
    if (lane == 0) out[idx] = s + bias;
}

// ---------------- K7: GRU gates + residual ----------------
__global__ void k7_gru(const float* __restrict__ hprev, float* __restrict__ d_out) {
    int i = threadIdx.x;
    float r = 1.f / (1.f + expf(-(g_gi[i] + g_gh[i])));
    float z = 1.f / (1.f + expf(-(g_gi[H + i] + g_gh[H + i])));
    float n = tanhf(g_gi[2 * H + i] + r * g_gh[2 * H + i]);
    float hp = hprev[i];
    float h = (1.f - z) * n + z * hp;
    d_out[V + i] = h;
    g_ov[i] = g_context[i] + h;
}

// ---------------- K8: logits = outW @ ov + outb ----------------
__global__ void __launch_bounds__(256) k8_logits(const float* __restrict__ outW,
                                                 const float* __restrict__ outb,
                                                 float* __restrict__ d_out) {
    __shared__ float4 ov[H / 4];
    int t = threadIdx.x;
    ov[t] = ((const float4*)g_ov)[t];
    __syncthreads();
    int warp = t >> 5, lane = t & 31;
    int v = blockIdx.x * 8 + warp;
    const float4* w4 = (const float4*)(outW + (size_t)v * H);
    float s = 0.f;
#pragma unroll
    for (int i = 0; i < 8; i++) {
        float4 a = w4[lane + 32 * i];
        float4 b = ov[lane + 32 * i];
        s += a.x * b.x + a.y * b.y + a.z * b.z + a.w * b.w;
    }
    s = warp_sum(s);
    if (lane == 0) d_out[v] = s + outb[v];
}

// ---------------- launch ----------------
extern "C" void kernel_launch(void* const* d_in, const int* in_sizes, int n_in,
                              void* d_out, int out_size) {
    const int* tok = (const int*)d_in[0];
    const float* hidden = (const float*)d_in[1];
    const float* enc = (const float*)d_in[2];
    const float* emb = (const float*)d_in[3];
    const float* wW = (const float*)d_in[4];
    const float* wb = (const float*)d_in[5];
    const float* uW = (const float*)d_in[6];
    const float* ub = (const float*)d_in[7];
    const float* vW = (const float*)d_in[8];
    const float* cW = (const float*)d_in[9];
    const float* cb = (const float*)d_in[10];
    const float* w_ih = (const float*)d_in[11];
    const float* b_ih = (const float*)d_in[12];
    const float* w_hh = (const float*)d_in[13];
    const float* b_hh = (const float*)d_in[14];
    const float* outW = (const float*)d_in[15];
    const float* outb = (const float*)d_in[16];
    float* out = (float*)d_out;

    cudaFuncSetAttribute(k2_scores, cudaFuncAttributeMaxDynamicSharedMemorySize, SMEM_DYN);

    k_prologue<<<L + H + 128, 256>>>(enc, uW, hidden, wW, wb, ub);
    k2_scores<<<dim3(L / 128, H / 128), 256, SMEM_DYN>>>(vW);
    k3_softmax<<<1, 1024>>>(out + V + H);
    k4_context<<<L / 64, 1024>>>(enc);
    k5_combine<<<128, 256>>>(cW, cb, emb, tok);
    k6_gru_gemv<<<(6 * H) / 8, 256>>>(w_ih, b_ih, w_hh, b_hh, hidden);
    k7_gru<<<1, 1024>>>(hidden, out);
    k8_logits<<<V / 8, 256>>>(outW, outb, out);
}

// round 5
// speedup vs baseline: 1.7492x; 1.7492x over previous
#include <cuda_runtime.h>
#include <cuda_bf16.h>
#include <math.h>
#include <stdint.h>

#define H 1024
#define V 32000
#define L 4096
#define KP 3072          // expanded K: 3 bf16 terms per fp32
#define NC 48            // K chunks of 64 bf16

// ---------------- device scratch ----------------
__device__ __nv_bfloat16 g_encb[(size_t)L * KP];   // 24 MB
__device__ __nv_bfloat16 g_uWb[(size_t)H * KP];    // 6 MB
__device__ float g_scores[L];
__device__ float g_q[H];
__device__ float g_attn[L];
__device__ float g_context[H];
__device__ float g_x[H];
__device__ float g_gi[3 * H];
__device__ float g_gh[3 * H];
__device__ float g_ov[H];

// ---------------- helpers ----------------
__device__ __forceinline__ uint32_t smem_u32(const void* p) {
    uint32_t a;
    asm("{ .reg .u64 t; cvta.to.shared.u64 t, %1; cvt.u32.u64 %0, t; }" : "=r"(a) : "l"(p));
    return a;
}
__device__ __forceinline__ uint32_t sw(uint32_t off) {   // Swizzle<3,4,3> on 128B rows
    return off ^ ((off >> 3) & 0x70u);
}
#define CP_ASYNC16(dst, src) \
    asm volatile("cp.async.cg.shared.global [%0], [%1], 16;" :: "r"(dst), "l"(src) : "memory")
#define CP_COMMIT() asm volatile("cp.async.commit_group;" ::: "memory")
#define CP_WAIT(n)  asm volatile("cp.async.wait_group %0;" :: "n"(n) : "memory")
#define LDSM_X4(r, a) \
    asm volatile("ldmatrix.sync.aligned.m8n8.x4.shared.b16 {%0,%1,%2,%3}, [%4];" \
                 : "=r"((r)[0]), "=r"((r)[1]), "=r"((r)[2]), "=r"((r)[3]) : "r"(a))

__device__ __forceinline__ void mma_bf16(float* c, const uint32_t* a, uint32_t b0, uint32_t b1) {
    asm volatile("mma.sync.aligned.m16n8k16.row.col.f32.bf16.bf16.f32 "
                 "{%0,%1,%2,%3}, {%4,%5,%6,%7}, {%8,%9}, {%0,%1,%2,%3};"
                 : "+f"(c[0]), "+f"(c[1]), "+f"(c[2]), "+f"(c[3])
                 : "r"(a[0]), "r"(a[1]), "r"(a[2]), "r"(a[3]), "r"(b0), "r"(b1));
}

__device__ __forceinline__ float warp_sum(float v) {
#pragma unroll
    for (int o = 16; o; o >>= 1) v += __shfl_xor_sync(0xffffffffu, v, o);
    return v;
}
__device__ __forceinline__ float warp_max(float v) {
#pragma unroll
    for (int o = 16; o; o >>= 1) v = fmaxf(v, __shfl_xor_sync(0xffffffffu, v, o));
    return v;
}

// pack two bf16 into u32
__device__ __forceinline__ uint32_t pk(__nv_bfloat16 a, __nv_bfloat16 b) {
    uint16_t ua = *(uint16_t*)&a, ub = *(uint16_t*)&b;
    return (uint32_t)ua | ((uint32_t)ub << 16);
}

// ---------------- fused prologue ----------------
// blocks [0,L): convert enc row -> [hi,hi,lo], zero g_scores[b]
// blocks [L,L+H): convert uW row -> [hi,lo,hi], zero g_context
// blocks [L+H, L+H+128): k1: q = wW@h0 + wb + ub (8 rows/block)
__global__ void __launch_bounds__(256) k_prologue(const float* __restrict__ enc,
                                                  const float* __restrict__ uW,
                                                  const float* __restrict__ h0,
                                                  const float* __restrict__ wW,
                                                  const float* __restrict__ wb,
                                                  const float* __restrict__ ub) {
    int b = blockIdx.x;
    int tid = threadIdx.x;
    if (b < L + H) {
        bool isA = (b < L);
        int r = isA ? b : b - L;
        const float4* src = (const float4*)((isA ? enc : uW) + (size_t)r * H);
        uint32_t* dst = (uint32_t*)((isA ? g_encb : g_uWb) + (size_t)r * KP);
        if (tid == 0) {
            if (isA) g_scores[r] = 0.f;
            else g_context[r] = 0.f;
        }
        float4 v = src[tid];
        float xs[4] = {v.x, v.y, v.z, v.w};
        __nv_bfloat16 hi[4], lo[4];
#pragma unroll
        for (int j = 0; j < 4; j++) {
            hi[j] = __float2bfloat16(xs[j]);
            lo[j] = __float2bfloat16(xs[j] - __bfloat162float(hi[j]));
        }
        uint32_t w[6];
        if (isA) {   // per element: hi,hi,lo
            w[0] = pk(hi[0], hi[0]); w[1] = pk(lo[0], hi[1]); w[2] = pk(hi[1], lo[1]);
            w[3] = pk(hi[2], hi[2]); w[4] = pk(lo[2], hi[3]); w[5] = pk(hi[3], lo[3]);
        } else {     // per element: hi,lo,hi
            w[0] = pk(hi[0], lo[0]); w[1] = pk(hi[0], hi[1]); w[2] = pk(lo[1], hi[1]);
            w[3] = pk(hi[2], lo[2]); w[4] = pk(hi[2], hi[3]); w[5] = pk(lo[3], hi[3]);
        }
        uint32_t* o = dst + tid * 6;
#pragma unroll
        for (int j = 0; j < 6; j++) o[j] = w[j];
    } else {
        int warp = ((b - L - H) << 3) + (tid >> 5);
        int lane = tid & 31;
        const float4* row = (const float4*)(wW + (size_t)warp * H);
        const float4* h4 = (const float4*)h0;
        float s = 0.f;
#pragma unroll
        for (int i = 0; i < 8; i++) {
            float4 a = row[lane + 32 * i];
            float4 hh = h4[lane + 32 * i];
            s += a.x * hh.x + a.y * hh.y + a.z * hh.z + a.w * hh.w;
        }
        s = warp_sum(s);
        if (lane == 0) g_q[warp] = s + wb[warp] + ub[warp];
    }
}

// ---------------- K2: mma.sync scores GEMM ----------------
// g_scores[l] += sum_{n in tile} vW[n]*tanh(q[n] + enc[l,:]·uW[n,:])
// 128x128 tile, Kc=64 bf16, cp.async double buffer, 8 warps 4x2, warp=32x64.
#define SMEM_DYN (2 * 32768 + 1024)

__global__ void __launch_bounds__(256, 2) k2_scores(const float* __restrict__ vW) {
    extern __shared__ char dsm[];
    __shared__ float sq[128], sv[128], sred[128][2];

    uint32_t sbase = (smem_u32(dsm) + 1023u) & ~1023u;
    int tid = threadIdx.x, wid = tid >> 5, lane = tid & 31;
    int wm = wid & 3, wn = wid >> 2;
    int bm = blockIdx.x * 128, bn = blockIdx.y * 128;

    if (tid < 128) { sq[tid] = g_q[bn + tid]; sv[tid] = vW[bn + tid]; }

    const __nv_bfloat16* gA = g_encb + (size_t)bm * KP;
    const __nv_bfloat16* gB = g_uWb + (size_t)bn * KP;

    int lr[4], lc[4];
    uint32_t loff[4];
#pragma unroll
    for (int i = 0; i < 4; i++) {
        int idx = tid + 256 * i;
        lr[i] = idx >> 3;
        lc[i] = idx & 7;
        loff[i] = sw((uint32_t)(lr[i] * 128 + lc[i] * 16));
    }

#define LOAD_CHUNK(c, buf) do { \
    uint32_t s_ = sbase + (buf) * 32768u; \
    _Pragma("unroll") \
    for (int i_ = 0; i_ < 4; i_++) { \
        const __nv_bfloat16* a_ = gA + (size_t)lr[i_] * KP + (c) * 64 + lc[i_] * 8; \
        const __nv_bfloat16* b_ = gB + (size_t)lr[i_] * KP + (c) * 64 + lc[i_] * 8; \
        CP_ASYNC16(s_ + loff[i_], a_); \
        CP_ASYNC16(s_ + 16384u + loff[i_], b_); \
    } \
    CP_COMMIT(); \
} while (0)

    float acc[2][8][4] = {};

    LOAD_CHUNK(0, 0);

    uint32_t aRow[2], bRow[4];
#pragma unroll
    for (int mt = 0; mt < 2; mt++)
        aRow[mt] = (uint32_t)((wm * 32 + mt * 16 + (lane & 15)) * 128 + (lane >> 4) * 16);
#pragma unroll
    for (int bp = 0; bp < 4; bp++)
        bRow[bp] = (uint32_t)((wn * 64 + bp * 16 + (lane & 15)) * 128 + (lane >> 4) * 16);

    for (int c = 0; c < NC; c++) {
        if (c + 1 < NC) {
            LOAD_CHUNK(c + 1, (c + 1) & 1);
            CP_WAIT(1);
        } else {
            CP_WAIT(0);
        }
        __syncthreads();
        uint32_t sA = sbase + (uint32_t)(c & 1) * 32768u;
        uint32_t sB = sA + 16384u;
#pragma unroll
        for (int ks = 0; ks < 4; ks++) {
            uint32_t afr[2][4];
#pragma unroll
            for (int mt = 0; mt < 2; mt++)
                LDSM_X4(afr[mt], sA + sw(aRow[mt] + ks * 32));
            uint32_t bfr[4][4];
#pragma unroll
            for (int bp = 0; bp < 4; bp++)
                LDSM_X4(bfr[bp], sB + sw(bRow[bp] + ks * 32));
#pragma unroll
            for (int mt = 0; mt < 2; mt++)
#pragma unroll
                for (int nt = 0; nt < 8; nt++) {
                    uint32_t b0 = bfr[nt >> 1][nt & 1];
                    uint32_t b1 = bfr[nt >> 1][(nt & 1) + 2];
                    mma_bf16(acc[mt][nt], afr[mt], b0, b1);
                }
        }
        __syncthreads();
    }

    // ---- epilogue: weighted tanh row reduction ----
    int cb = wn * 64;
    int c0 = 2 * (lane & 3);
    float p[2][2];
#pragma unroll
    for (int mt = 0; mt < 2; mt++)
#pragma unroll
        for (int half = 0; half < 2; half++) {
            float s = 0.f;
#pragma unroll
            for (int nt = 0; nt < 8; nt++) {
#pragma unroll
                for (int j = 0; j < 2; j++) {
                    int n = cb + nt * 8 + c0 + j;
                    s += sv[n] * tanhf(sq[n] + acc[mt][nt][half * 2 + j]);
                }
            }
            p[mt][half] = s;
        }
#pragma unroll
    for (int mt = 0; mt < 2; mt++)
#pragma unroll
        for (int half = 0; half < 2; half++) {
            float s = p[mt][half];
            s += __shfl_xor_sync(0xffffffffu, s, 1);
            s += __shfl_xor_sync(0xffffffffu, s, 2);
            p[mt][half] = s;
        }
    if ((lane & 3) == 0) {
#pragma unroll
        for (int mt = 0; mt < 2; mt++)
#pragma unroll
            for (int half = 0; half < 2; half++)
                sred[wm * 32 + mt * 16 + half * 8 + (lane >> 2)][wn] = p[mt][half];
    }
    __syncthreads();
    if (tid < 128)
        atomicAdd(&g_scores[bm + tid], sred[tid][0] + sred[tid][1]);
}

// ---------------- K3: softmax ----------------
__global__ void k3_softmax(float* __restrict__ out_attn) {
    __shared__ float sm[32];
    int t = threadIdx.x;
    float v[4];
    float mx = -1e30f;
#pragma unroll
    for (int i = 0; i < 4; i++) {
        v[i] = g_scores[t + 1024 * i];
        mx = fmaxf(mx, v[i]);
    }
    mx = warp_max(mx);
    if ((t & 31) == 0) sm[t >> 5] = mx;
    __syncthreads();
    if (t < 32) {
        float m2 = warp_max(sm[t]);
        if (t == 0) sm[0] = m2;
    }
    __syncthreads();
    mx = sm[0];
    __syncthreads();
    float se = 0.f;
#pragma unroll
    for (int i = 0; i < 4; i++) {
        v[i] = expf(v[i] - mx);
        se += v[i];
    }
    se = warp_sum(se);
    if ((t & 31) == 0) sm[t >> 5] = se;
    __syncthreads();
    if (t < 32) {
        float s2 = warp_sum(sm[t]);
        if (t == 0) sm[0] = s2;
    }
    __syncthreads();
    float inv = 1.f / sm[0];
#pragma unroll
    for (int i = 0; i < 4; i++) {
        float a = v[i] * inv;
        g_attn[t + 1024 * i] = a;
        out_attn[t + 1024 * i] = a;
    }
}

// ---------------- K4: context = attn^T @ enc (256 blocks x 16 rows) ----------------
__global__ void __launch_bounds__(256) k4_context(const float* __restrict__ enc) {
    __shared__ float aw[16];
    int t = threadIdx.x;
    int l0 = blockIdx.x * 16;
    if (t < 16) aw[t] = g_attn[l0 + t];
    __syncthreads();
    float4 s = make_float4(0.f, 0.f, 0.f, 0.f);
#pragma unroll
    for (int l = 0; l < 16; l++) {
        float4 e = ((const float4*)(enc + (size_t)(l0 + l) * H))[t];
        float w = aw[l];
        s.x += w * e.x; s.y += w * e.y; s.z += w * e.z; s.w += w * e.w;
    }
    atomicAdd(&g_context[4 * t + 0], s.x);
    atomicAdd(&g_context[4 * t + 1], s.y);
    atomicAdd(&g_context[4 * t + 2], s.z);
    atomicAdd(&g_context[4 * t + 3], s.w);
}

// ---------------- K5: x = relu(cW @ [context;embedded] + cb) ----------------
__global__ void k5_combine(const float* __restrict__ cW, const float* __restrict__ cb,
                           const float* __restrict__ emb, const int* __restrict__ tok) {
    int warp = (blockIdx.x * blockDim.x + threadIdx.x) >> 5;
    int lane = threadIdx.x & 31;
    if (warp >= H) return;
    const float4* r1 = (const float4*)(cW + (size_t)warp * 2 * H);
    const float4* r2 = r1 + H / 4;
    const float4* c4 = (const float4*)g_context;
    const float4* e4 = (const float4*)(emb + (size_t)tok[0] * H);
    float s = 0.f;
#pragma unroll
    for (int i = 0; i < 8; i++) {
        float4 a = r1[lane + 32 * i];
        float4 b = c4[lane + 32 * i];
        s += a.x * b.x + a.y * b.y + a.z * b.z + a.w * b.w;
        float4 a2 = r2[lane + 32 * i];
        float4 b2 = e4[lane + 32 * i];
        s += a2.x * b2.x + a2.y * b2.y + a2.z * b2.z + a2.w * b2.w;
    }
    s = warp_sum(s);
    if (lane == 0) g_x[warp] = fmaxf(s + cb[warp], 0.f);
}

// ---------------- K6: GRU gate GEMVs ----------------
__global__ void k6_gru_gemv(const float* __restrict__ w_ih, const float* __restrict__ b_ih,
                            const float* __restrict__ w_hh, const float* __restrict__ b_hh,
                            const float* __restrict__ hprev) {
    int warp = (blockIdx.x * blockDim.x + threadIdx.x) >> 5;
    int lane = threadIdx.x & 31;
    if (warp >= 6 * H) return;
    const float4* row;
    const float4* vec;
    float bias;
    float* out;
    int idx;
    if (warp < 3 * H) {
        idx = warp;
        row = (const float4*)(w_ih + (size_t)idx * H);
        vec = (const float4*)g_x;
        bias = b_ih[idx];
        out = g_gi;
    } else {
        idx = warp - 3 * H;
        row = (const float4*)(w_hh + (size_t)idx * H);
        vec = (const float4*)hprev;
        bias = b_hh[idx];
        out = g_gh;
    }
    float s = 0.f;
#pragma unroll
    for (int i = 0; i < 8; i++) {
        float4 a = row[lane + 32 * i];
        float4 b = vec[lane + 32 * i];
        s += a.x * b.x + a.y * b.y + a.z * b.z + a.w * b.w;
    }
    s = warp_sum(s);
    if (lane == 0) out[idx] = s + bias;
}

// ---------------- K7: GRU gates + residual ----------------
__global__ void k7_gru(const float* __restrict__ hprev, float* __restrict__ d_out) {
    int i = threadIdx.x;
    float r = 1.f / (1.f + expf(-(g_gi[i] + g_gh[i])));
    float z = 1.f / (1.f + expf(-(g_gi[H + i] + g_gh[H + i])));
    float n = tanhf(g_gi[2 * H + i] + r * g_gh[2 * H + i]);
    float hp = hprev[i];
    float h = (1.f - z) * n + z * hp;
    d_out[V + i] = h;
    g_ov[i] = g_context[i] + h;
}

// ---------------- K8: logits = outW @ ov + outb ----------------
__global__ void __launch_bounds__(256) k8_logits(const float* __restrict__ outW,
                                                 const float* __restrict__ outb,
                                                 float* __restrict__ d_out) {
    __shared__ float4 ov[H / 4];
    int t = threadIdx.x;
    ov[t] = ((const float4*)g_ov)[t];
    __syncthreads();
    int warp = t >> 5, lane = t & 31;
    int v = blockIdx.x * 8 + warp;
    const float4* w4 = (const float4*)(outW + (size_t)v * H);
    float s = 0.f;
#pragma unroll
    for (int i = 0; i < 8; i++) {
        float4 a = w4[lane + 32 * i];
        float4 b = ov[lane + 32 * i];
        s += a.x * b.x + a.y * b.y + a.z * b.z + a.w * b.w;
    }
    s = warp_sum(s);
    if (lane == 0) d_out[v] = s + outb[v];
}

// ---------------- launch ----------------
extern "C" void kernel_launch(void* const* d_in, const int* in_sizes, int n_in,
                              void* d_out, int out_size) {
    const int* tok = (const int*)d_in[0];
    const float* hidden = (const float*)d_in[1];
    const float* enc = (const float*)d_in[2];
    const float* emb = (const float*)d_in[3];
    const float* wW = (const float*)d_in[4];
    const float* wb = (const float*)d_in[5];
    const float* uW = (const float*)d_in[6];
    const float* ub = (const float*)d_in[7];
    const float* vW = (const float*)d_in[8];
    const float* cW = (const float*)d_in[9];
    const float* cb = (const float*)d_in[10];
    const float* w_ih = (const float*)d_in[11];
    const float* b_ih = (const float*)d_in[12];
    const float* w_hh = (const float*)d_in[13];
    const float* b_hh = (const float*)d_in[14];
    const float* outW = (const float*)d_in[15];
    const float* outb = (const float*)d_in[16];
    float* out = (float*)d_out;

    cudaFuncSetAttribute(k2_scores, cudaFuncAttributeMaxDynamicSharedMemorySize, SMEM_DYN);

    k_prologue<<<L + H + 128, 256>>>(enc, uW, hidden, wW, wb, ub);
    k2_scores<<<dim3(L / 128, H / 128), 256, SMEM_DYN>>>(vW);
    k3_softmax<<<1, 1024>>>(out + V + H);
    k4_context<<<256, 256>>>(enc);
    k5_combine<<<128, 256>>>(cW, cb, emb, tok);
    k6_gru_gemv<<<(6 * H) / 8, 256>>>(w_ih, b_ih, w_hh, b_hh, hidden);
    k7_gru<<<1, 1024>>>(hidden, out);
    k8_logits<<<V / 8, 256>>>(outW, outb, out);
}

// round 6
// speedup vs baseline: 2.0581x; 1.1766x over previous
#include <cuda_runtime.h>
#include <cuda_fp16.h>
#include <math.h>
#include <stdint.h>

#define H 1024
#define V 32000
#define L 4096
#define NC 32            // K chunks of 64 fp16 over K'=2048

// ---------------- device scratch ----------------
__device__ __half g_ench[(size_t)L * 1024];   // enc hi, 8 MB
__device__ __half g_uWh[(size_t)H * 2048];    // uW [hi|lo], 4 MB
__device__ float g_scores[L];
__device__ float g_q[H];
__device__ float g_attn[L];
__device__ float g_context[H];
__device__ float g_x[H];
__device__ float g_gi[3 * H];
__device__ float g_gh[3 * H];
__device__ float g_ov[H];

// ---------------- helpers ----------------
__device__ __forceinline__ uint32_t smem_u32(const void* p) {
    uint32_t a;
    asm("{ .reg .u64 t; cvta.to.shared.u64 t, %1; cvt.u32.u64 %0, t; }" : "=r"(a) : "l"(p));
    return a;
}
__device__ __forceinline__ uint32_t sw(uint32_t off) {   // Swizzle<3,4,3> on 128B rows
    return off ^ ((off >> 3) & 0x70u);
}
#define CP_ASYNC16(dst, src) \
    asm volatile("cp.async.cg.shared.global [%0], [%1], 16;" :: "r"(dst), "l"(src) : "memory")
#define CP_COMMIT() asm volatile("cp.async.commit_group;" ::: "memory")
#define CP_WAIT(n)  asm volatile("cp.async.wait_group %0;" :: "n"(n) : "memory")
#define LDSM_X4(r, a) \
    asm volatile("ldmatrix.sync.aligned.m8n8.x4.shared.b16 {%0,%1,%2,%3}, [%4];" \
                 : "=r"((r)[0]), "=r"((r)[1]), "=r"((r)[2]), "=r"((r)[3]) : "r"(a))

__device__ __forceinline__ void mma_f16(float* c, const uint32_t* a, uint32_t b0, uint32_t b1) {
    asm volatile("mma.sync.aligned.m16n8k16.row.col.f32.f16.f16.f32 "
                 "{%0,%1,%2,%3}, {%4,%5,%6,%7}, {%8,%9}, {%0,%1,%2,%3};"
                 : "+f"(c[0]), "+f"(c[1]), "+f"(c[2]), "+f"(c[3])
                 : "r"(a[0]), "r"(a[1]), "r"(a[2]), "r"(a[3]), "r"(b0), "r"(b1));
}

__device__ __forceinline__ float warp_sum(float v) {
#pragma unroll
    for (int o = 16; o; o >>= 1) v += __shfl_xor_sync(0xffffffffu, v, o);
    return v;
}
__device__ __forceinline__ float warp_max(float v) {
#pragma unroll
    for (int o = 16; o; o >>= 1) v = fmaxf(v, __shfl_xor_sync(0xffffffffu, v, o));
    return v;
}
__device__ __forceinline__ uint32_t pkh(__half a, __half b) {
    uint16_t ua = *(uint16_t*)&a, ub = *(uint16_t*)&b;
    return (uint32_t)ua | ((uint32_t)ub << 16);
}

// ---------------- fused prologue ----------------
// blocks [0,L): enc row -> fp16 hi, zero g_scores[b]
// blocks [L,L+H): uW row -> fp16 [hi|lo], zero g_context
// blocks [L+H, L+H+128): k1: q = wW@h0 + wb + ub (8 rows/block)
__global__ void __launch_bounds__(256) k_prologue(const float* __restrict__ enc,
                                                  const float* __restrict__ uW,
                                                  const float* __restrict__ h0,
                                                  const float* __restrict__ wW,
                                                  const float* __restrict__ wb,
                                                  const float* __restrict__ ub) {
    int b = blockIdx.x;
    int tid = threadIdx.x;
    if (b < L) {
        if (tid == 0) g_scores[b] = 0.f;
        float4 v = ((const float4*)(enc + (size_t)b * H))[tid];
        __half h0v = __float2half_rn(v.x), h1 = __float2half_rn(v.y);
        __half h2 = __float2half_rn(v.z), h3 = __float2half_rn(v.w);
        uint2 w = make_uint2(pkh(h0v, h1), pkh(h2, h3));
        ((uint2*)(g_ench + (size_t)b * 1024))[tid] = w;
    } else if (b < L + H) {
        int r = b - L;
        if (tid == 0) g_context[r] = 0.f;
        float4 v = ((const float4*)(uW + (size_t)r * H))[tid];
        float xs[4] = {v.x, v.y, v.z, v.w};
        __half hi[4], lo[4];
#pragma unroll
        for (int j = 0; j < 4; j++) {
            hi[j] = __float2half_rn(xs[j]);
            lo[j] = __float2half_rn(xs[j] - __half2float(hi[j]));
        }
        uint32_t* dst = (uint32_t*)(g_uWh + (size_t)r * 2048);
        dst[tid * 2] = pkh(hi[0], hi[1]);
        dst[tid * 2 + 1] = pkh(hi[2], hi[3]);
        dst[512 + tid * 2] = pkh(lo[0], lo[1]);
        dst[512 + tid * 2 + 1] = pkh(lo[2], lo[3]);
    } else {
        int warp = ((b - L - H) << 3) + (tid >> 5);
        int lane = tid & 31;
        const float4* row = (const float4*)(wW + (size_t)warp * H);
        const float4* h4 = (const float4*)h0;
        float s = 0.f;
#pragma unroll
        for (int i = 0; i < 8; i++) {
            float4 a = row[lane + 32 * i];
            float4 hh = h4[lane + 32 * i];
            s += a.x * hh.x + a.y * hh.y + a.z * hh.z + a.w * hh.w;
        }
        s = warp_sum(s);
        if (lane == 0) g_q[warp] = s + wb[warp] + ub[warp];
    }
}

// ---------------- K2: mma.sync fp16 scores GEMM ----------------
// S = Ah @ (Bh+Bl)^T over K'=2048: chunks 0..15 use (Ah, Bh), 16..31 use (Ah, Bl).
// g_scores[l] += sum_n vW[n]*tanh(q[n] + S[l,n]); 128x128 tile, Kc=64, 8 warps 4x2.
#define SMEM_DYN (2 * 32768 + 1024)

__global__ void __launch_bounds__(256, 2) k2_scores(const float* __restrict__ vW) {
    extern __shared__ char dsm[];
    __shared__ float sq[128], sv[128], sred[128][2];

    uint32_t sbase = (smem_u32(dsm) + 1023u) & ~1023u;
    int tid = threadIdx.x, wid = tid >> 5, lane = tid & 31;
    int wm = wid & 3, wn = wid >> 2;
    int bm = blockIdx.x * 128, bn = blockIdx.y * 128;

    if (tid < 128) { sq[tid] = g_q[bn + tid]; sv[tid] = vW[bn + tid]; }

    const __half* gA = g_ench + (size_t)bm * 1024;
    const __half* gB = g_uWh + (size_t)bn * 2048;

    int lr[4], lc[4];
    uint32_t loff[4];
#pragma unroll
    for (int i = 0; i < 4; i++) {
        int idx = tid + 256 * i;
        lr[i] = idx >> 3;
        lc[i] = idx & 7;
        loff[i] = sw((uint32_t)(lr[i] * 128 + lc[i] * 16));
    }

#define LOAD_CHUNK(c, buf) do { \
    uint32_t ao_ = ((uint32_t)(c) & 15u) * 64u; \
    uint32_t bo_ = (uint32_t)(c) * 64u; \
    uint32_t s_ = sbase + (buf) * 32768u; \
    _Pragma("unroll") \
    for (int i_ = 0; i_ < 4; i_++) { \
        const __half* a_ = gA + (size_t)lr[i_] * 1024 + ao_ + lc[i_] * 8; \
        const __half* b_ = gB + (size_t)lr[i_] * 2048 + bo_ + lc[i_] * 8; \
        CP_ASYNC16(s_ + loff[i_], a_); \
        CP_ASYNC16(s_ + 16384u + loff[i_], b_); \
    } \
    CP_COMMIT(); \
} while (0)

    float acc[2][8][4] = {};

    LOAD_CHUNK(0, 0);

    uint32_t aRow[2], bRow[4];
#pragma unroll
    for (int mt = 0; mt < 2; mt++)
        aRow[mt] = (uint32_t)((wm * 32 + mt * 16 + (lane & 15)) * 128 + (lane >> 4) * 16);
#pragma unroll
    for (int bp = 0; bp < 4; bp++)
        bRow[bp] = (uint32_t)((wn * 64 + bp * 16 + (lane & 15)) * 128 + (lane >> 4) * 16);

    for (int c = 0; c < NC; c++) {
        if (c + 1 < NC) {
            LOAD_CHUNK(c + 1, (c + 1) & 1);
            CP_WAIT(1);
        } else {
            CP_WAIT(0);
        }
        __syncthreads();
        uint32_t sA = sbase + (uint32_t)(c & 1) * 32768u;
        uint32_t sB = sA + 16384u;
#pragma unroll
        for (int ks = 0; ks < 4; ks++) {
            uint32_t afr[2][4];
#pragma unroll
            for (int mt = 0; mt < 2; mt++)
                LDSM_X4(afr[mt], sA + sw(aRow[mt] + ks * 32));
            uint32_t bfr[4][4];
#pragma unroll
            for (int bp = 0; bp < 4; bp++)
                LDSM_X4(bfr[bp], sB + sw(bRow[bp] + ks * 32));
#pragma unroll
            for (int mt = 0; mt < 2; mt++)
#pragma unroll
                for (int nt = 0; nt < 8; nt++) {
                    uint32_t b0 = bfr[nt >> 1][nt & 1];
                    uint32_t b1 = bfr[nt >> 1][(nt & 1) + 2];
                    mma_f16(acc[mt][nt], afr[mt], b0, b1);
                }
        }
        __syncthreads();
    }

    // ---- epilogue: weighted tanh row reduction ----
    int cb = wn * 64;
    int c0 = 2 * (lane & 3);
    float p[2][2];
#pragma unroll
    for (int mt = 0; mt < 2; mt++)
#pragma unroll
        for (int half = 0; half < 2; half++) {
            float s = 0.f;
#pragma unroll
            for (int nt = 0; nt < 8; nt++) {
#pragma unroll
                for (int j = 0; j < 2; j++) {
                    int n = cb + nt * 8 + c0 + j;
                    s += sv[n] * tanhf(sq[n] + acc[mt][nt][half * 2 + j]);
                }
            }
            p[mt][half] = s;
        }
#pragma unroll
    for (int mt = 0; mt < 2; mt++)
#pragma unroll
        for (int half = 0; half < 2; half++) {
            float s = p[mt][half];
            s += __shfl_xor_sync(0xffffffffu, s, 1);
            s += __shfl_xor_sync(0xffffffffu, s, 2);
            p[mt][half] = s;
        }
    if ((lane & 3) == 0) {
#pragma unroll
        for (int mt = 0; mt < 2; mt++)
#pragma unroll
            for (int half = 0; half < 2; half++)
                sred[wm * 32 + mt * 16 + half * 8 + (lane >> 2)][wn] = p[mt][half];
    }
    __syncthreads();
    if (tid < 128)
        atomicAdd(&g_scores[bm + tid], sred[tid][0] + sred[tid][1]);
}

// ---------------- K3: softmax ----------------
__global__ void k3_softmax(float* __restrict__ out_attn) {
    __shared__ float sm[32];
    int t = threadIdx.x;
    float v[4];
    float mx = -1e30f;
#pragma unroll
    for (int i = 0; i < 4; i++) {
        v[i] = g_scores[t + 1024 * i];
        mx = fmaxf(mx, v[i]);
    }
    mx = warp_max(mx);
    if ((t & 31) == 0) sm[t >> 5] = mx;
    __syncthreads();
    if (t < 32) {
        float m2 = warp_max(sm[t]);
        if (t == 0) sm[0] = m2;
    }
    __syncthreads();
    mx = sm[0];
    __syncthreads();
    float se = 0.f;
#pragma unroll
    for (int i = 0; i < 4; i++) {
        v[i] = expf(v[i] - mx);
        se += v[i];
    }
    se = warp_sum(se);
    if ((t & 31) == 0) sm[t >> 5] = se;
    __syncthreads();
    if (t < 32) {
        float s2 = warp_sum(sm[t]);
        if (t == 0) sm[0] = s2;
    }
    __syncthreads();
    float inv = 1.f / sm[0];
#pragma unroll
    for (int i = 0; i < 4; i++) {
        float a = v[i] * inv;
        g_attn[t + 1024 * i] = a;
        out_attn[t + 1024 * i] = a;
    }
}

// ---------------- K4: context = attn^T @ enc (512 blocks x 8 rows, MLP=8) ----------------
__global__ void __launch_bounds__(256) k4_context(const float* __restrict__ enc) {
    __shared__ float aw[8];
    int t = threadIdx.x;
    int l0 = blockIdx.x * 8;
    if (t < 8) aw[t] = g_attn[l0 + t];
    __syncthreads();
    float4 e[8];
#pragma unroll
    for (int l = 0; l < 8; l++)
        e[l] = ((const float4*)(enc + (size_t)(l0 + l) * H))[t];
    float4 s = make_float4(0.f, 0.f, 0.f, 0.f);
#pragma unroll
    for (int l = 0; l < 8; l++) {
        float w = aw[l];
        s.x += w * e[l].x; s.y += w * e[l].y; s.z += w * e[l].z; s.w += w * e[l].w;
    }
    atomicAdd(&g_context[4 * t + 0], s.x);
    atomicAdd(&g_context[4 * t + 1], s.y);
    atomicAdd(&g_context[4 * t + 2], s.z);
    atomicAdd(&g_context[4 * t + 3], s.w);
}

// ---------------- K5: x = relu(cW @ [context;embedded] + cb) ----------------
__global__ void k5_combine(const float* __restrict__ cW, const float* __restrict__ cb,
                           const float* __restrict__ emb, const int* __restrict__ tok) {
    int warp = (blockIdx.x * blockDim.x + threadIdx.x) >> 5;
    int lane = threadIdx.x & 31;
    if (warp >= H) return;
    const float4* r1 = (const float4*)(cW + (size_t)warp * 2 * H);
    const float4* r2 = r1 + H / 4;
    const float4* c4 = (const float4*)g_context;
    const float4* e4 = (const float4*)(emb + (size_t)tok[0] * H);
    float s = 0.f;
#pragma unroll
    for (int i = 0; i < 8; i++) {
        float4 a = r1[lane + 32 * i];
        float4 b = c4[lane + 32 * i];
        s += a.x * b.x + a.y * b.y + a.z * b.z + a.w * b.w;
        float4 a2 = r2[lane + 32 * i];
        float4 b2 = e4[lane + 32 * i];
        s += a2.x * b2.x + a2.y * b2.y + a2.z * b2.z + a2.w * b2.w;
    }
    s = warp_sum(s);
    if (lane == 0) g_x[warp] = fmaxf(s + cb[warp], 0.f);
}

// ---------------- K6: GRU gate GEMVs ----------------
__global__ void k6_gru_gemv(const float* __restrict__ w_ih, const float* __restrict__ b_ih,
                            const float* __restrict__ w_hh, const float* __restrict__ b_hh,
                            const float* __restrict__ hprev) {
    int warp = (blockIdx.x * blockDim.x + threadIdx.x) >> 5;
    int lane = threadIdx.x & 31;
    if (warp >= 6 * H) return;
    const float4* row;
    const float4* vec;
    float bias;
    float* out;
    int idx;
    if (warp < 3 * H) {
        idx = warp;
        row = (const float4*)(w_ih + (size_t)idx * H);
        vec = (const float4*)g_x;
        bias = b_ih[idx];
        out = g_gi;
    } else {
        idx = warp - 3 * H;
        row = (const float4*)(w_hh + (size_t)idx * H);
        vec = (const float4*)hprev;
        bias = b_hh[idx];
        out = g_gh;
    }
    float s = 0.f;
#pragma unroll
    for (int i = 0; i < 8; i++) {
        float4 a = row[lane + 32 * i];
        float4 b = vec[lane + 32 * i];
        s += a.x * b.x + a.y * b.y + a.z * b.z + a.w * b.w;
    }
    s = warp_sum(s);
    if (lane == 0) out[idx] = s + bias;
}

// ---------------- K7: GRU gates + residual ----------------
__global__ void k7_gru(const float* __restrict__ hprev, float* __restrict__ d_out) {
    int i = threadIdx.x;
    float r = 1.f / (1.f + expf(-(g_gi[i] + g_gh[i])));
    float z = 1.f / (1.f + expf(-(g_gi[H + i] + g_gh[H + i])));
    float n = tanhf(g_gi[2 * H + i] + r * g_gh[2 * H + i]);
    float hp = hprev[i];
    float h = (1.f - z) * n + z * hp;
    d_out[V + i] = h;
    g_ov[i] = g_context[i] + h;
}

// ---------------- K8: logits = outW @ ov + outb ----------------
__global__ void __launch_bounds__(256) k8_logits(const float* __restrict__ outW,
                                                 const float* __restrict__ outb,
                                                 float* __restrict__ d_out) {
    __shared__ float4 ov[H / 4];
    int t = threadIdx.x;
    ov[t] = ((const float4*)g_ov)[t];
    __syncthreads();
    int warp = t >> 5, lane = t & 31;
    int v = blockIdx.x * 8 + warp;
    const float4* w4 = (const float4*)(outW + (size_t)v * H);
    float s = 0.f;
#pragma unroll
    for (int i = 0; i < 8; i++) {
        float4 a = w4[lane + 32 * i];
        float4 b = ov[lane + 32 * i];
        s += a.x * b.x + a.y * b.y + a.z * b.z + a.w * b.w;
    }
    s = warp_sum(s);
    if (lane == 0) d_out[v] = s + outb[v];
}

// ---------------- launch ----------------
extern "C" void kernel_launch(void* const* d_in, const int* in_sizes, int n_in,
                              void* d_out, int out_size) {
    const int* tok = (const int*)d_in[0];
    const float* hidden = (const float*)d_in[1];
    const float* enc = (const float*)d_in[2];
    const float* emb = (const float*)d_in[3];
    const float* wW = (const float*)d_in[4];
    const float* wb = (const float*)d_in[5];
    const float* uW = (const float*)d_in[6];
    const float* ub = (const float*)d_in[7];
    const float* vW = (const float*)d_in[8];
    const float* cW = (const float*)d_in[9];
    const float* cb = (const float*)d_in[10];
    const float* w_ih = (const float*)d_in[11];
    const float* b_ih = (const float*)d_in[12];
    const float* w_hh = (const float*)d_in[13];
    const float* b_hh = (const float*)d_in[14];
    const float* outW = (const float*)d_in[15];
    const float* outb = (const float*)d_in[16];
    float* out = (float*)d_out;

    cudaFuncSetAttribute(k2_scores, cudaFuncAttributeMaxDynamicSharedMemorySize, SMEM_DYN);

    k_prologue<<<L + H + 128, 256>>>(enc, uW, hidden, wW, wb, ub);
    k2_scores<<<dim3(L / 128, H / 128), 256, SMEM_DYN>>>(vW);
    k3_softmax<<<1, 1024>>>(out + V + H);
    k4_context<<<512, 256>>>(enc);
    k5_combine<<<128, 256>>>(cW, cb, emb, tok);
    k6_gru_gemv<<<(6 * H) / 8, 256>>>(w_ih, b_ih, w_hh, b_hh, hidden);
    k7_gru<<<1, 1024>>>(hidden, out);
    k8_logits<<<V / 8, 256>>>(outW, outb, out);
}

// round 7
// speedup vs baseline: 2.8563x; 1.3878x over previous
#include <cuda_runtime.h>
#include <cuda_fp16.h>
#include <math.h>
#include <stdint.h>

#define H 1024
#define V 32000
#define L 4096
#define NC 16            // K chunks of 64 fp16 over K=1024

// ---------------- device scratch ----------------
__device__ __half g_ench[(size_t)L * 1024];   // enc fp16, 8 MB
__device__ __half g_uWh[(size_t)H * 1024];    // uW fp16, 2 MB
__device__ float g_cpart[64 * H];
__device__ float g_scores[L];
__device__ float g_q[H];
__device__ float g_attn[L];
__device__ float g_context[H];
__device__ float g_x[H];
__device__ float g_gi[3 * H];
__device__ float g_gh[3 * H];
__device__ float g_ov[H];

// ---------------- helpers ----------------
__device__ __forceinline__ uint32_t smem_u32(const void* p) {
    uint32_t a;
    asm("{ .reg .u64 t; cvta.to.shared.u64 t, %1; cvt.u32.u64 %0, t; }" : "=r"(a) : "l"(p));
    return a;
}
__device__ __forceinline__ uint32_t sw(uint32_t off) {   // Swizzle<3,4,3> on 128B rows
    return off ^ ((off >> 3) & 0x70u);
}
#define CP_ASYNC16(dst, src) \
    asm volatile("cp.async.cg.shared.global [%0], [%1], 16;" :: "r"(dst), "l"(src) : "memory")
#define CP_COMMIT() asm volatile("cp.async.commit_group;" ::: "memory")
#define CP_WAIT(n)  asm volatile("cp.async.wait_group %0;" :: "n"(n) : "memory")
#define LDSM_X4(r, a) \
    asm volatile("ldmatrix.sync.aligned.m8n8.x4.shared.b16 {%0,%1,%2,%3}, [%4];" \
                 : "=r"((r)[0]), "=r"((r)[1]), "=r"((r)[2]), "=r"((r)[3]) : "r"(a))

__device__ __forceinline__ void mma_f16(float* c, const uint32_t* a, uint32_t b0, uint32_t b1) {
    asm volatile("mma.sync.aligned.m16n8k16.row.col.f32.f16.f16.f32 "
                 "{%0,%1,%2,%3}, {%4,%5,%6,%7}, {%8,%9}, {%0,%1,%2,%3};"
                 : "+f"(c[0]), "+f"(c[1]), "+f"(c[2]), "+f"(c[3])
                 : "r"(a[0]), "r"(a[1]), "r"(a[2]), "r"(a[3]), "r"(b0), "r"(b1));
}

__device__ __forceinline__ float warp_sum(float v) {
#pragma unroll
    for (int o = 16; o; o >>= 1) v += __shfl_xor_sync(0xffffffffu, v, o);
    return v;
}
__device__ __forceinline__ float warp_max(float v) {
#pragma unroll
    for (int o = 16; o; o >>= 1) v = fmaxf(v, __shfl_xor_sync(0xffffffffu, v, o));
    return v;
}
__device__ __forceinline__ uint32_t pkh(__half a, __half b) {
    uint16_t ua = *(uint16_t*)&a, ub = *(uint16_t*)&b;
    return (uint32_t)ua | ((uint32_t)ub << 16);
}

// ---------------- fused prologue ----------------
// blocks [0,L): enc row -> fp16, zero g_scores[b]
// blocks [L,L+H): uW row -> fp16
// blocks [L+H, L+H+128): k1: q = wW@h0 + wb + ub (8 rows/block)
__global__ void __launch_bounds__(256) k_prologue(const float* __restrict__ enc,
                                                  const float* __restrict__ uW,
                                                  const float* __restrict__ h0,
                                                  const float* __restrict__ wW,
                                                  const float* __restrict__ wb,
                                                  const float* __restrict__ ub) {
    int b = blockIdx.x;
    int tid = threadIdx.x;
    if (b < L + H) {
        bool isA = (b < L);
        int r = isA ? b : b - L;
        if (isA && tid == 0) g_scores[r] = 0.f;
        const float4* src = (const float4*)((isA ? enc : uW) + (size_t)r * H);
        float4 v = src[tid];
        uint2 w = make_uint2(pkh(__float2half_rn(v.x), __float2half_rn(v.y)),
                             pkh(__float2half_rn(v.z), __float2half_rn(v.w)));
        __half* dst = (isA ? g_ench : g_uWh) + (size_t)r * 1024;
        ((uint2*)dst)[tid] = w;
    } else {
        int warp = ((b - L - H) << 3) + (tid >> 5);
        int lane = tid & 31;
        const float4* row = (const float4*)(wW + (size_t)warp * H);
        const float4* h4 = (const float4*)h0;
        float s = 0.f;
#pragma unroll
        for (int i = 0; i < 8; i++) {
            float4 a = row[lane + 32 * i];
            float4 hh = h4[lane + 32 * i];
            s += a.x * hh.x + a.y * hh.y + a.z * hh.z + a.w * hh.w;
        }
        s = warp_sum(s);
        if (lane == 0) g_q[warp] = s + wb[warp] + ub[warp];
    }
}

// ---------------- K2: mma.sync fp16 scores GEMM (K=1024) ----------------
// g_scores[l] += sum_n vW[n]*tanh(q[n] + enc[l,:]·uW[n,:])
// 128x128 tile, Kc=64, cp.async double buffer, 8 warps 4x2, warp=32x64.
#define SMEM_DYN (2 * 32768 + 1024)

__global__ void __launch_bounds__(256, 2) k2_scores(const float* __restrict__ vW) {
    extern __shared__ char dsm[];
    __shared__ float sq[128], sv[128], sred[128][2];

    uint32_t sbase = (smem_u32(dsm) + 1023u) & ~1023u;
    int tid = threadIdx.x, wid = tid >> 5, lane = tid & 31;
    int wm = wid & 3, wn = wid >> 2;
    int bm = blockIdx.x * 128, bn = blockIdx.y * 128;

    if (tid < 128) { sq[tid] = g_q[bn + tid]; sv[tid] = vW[bn + tid]; }

    const __half* gA = g_ench + (size_t)bm * 1024;
    const __half* gB = g_uWh + (size_t)bn * 1024;

    int lr[4], lc[4];
    uint32_t loff[4];
#pragma unroll
    for (int i = 0; i < 4; i++) {
        int idx = tid + 256 * i;
        lr[i] = idx >> 3;
        lc[i] = idx & 7;
        loff[i] = sw((uint32_t)(lr[i] * 128 + lc[i] * 16));
    }

#define LOAD_CHUNK(c, buf) do { \
    uint32_t o_ = (uint32_t)(c) * 64u; \
    uint32_t s_ = sbase + (buf) * 32768u; \
    _Pragma("unroll") \
    for (int i_ = 0; i_ < 4; i_++) { \
        const __half* a_ = gA + (size_t)lr[i_] * 1024 + o_ + lc[i_] * 8; \
        const __half* b_ = gB + (size_t)lr[i_] * 1024 + o_ + lc[i_] * 8; \
        CP_ASYNC16(s_ + loff[i_], a_); \
        CP_ASYNC16(s_ + 16384u + loff[i_], b_); \
    } \
    CP_COMMIT(); \
} while (0)

    float acc[2][8][4] = {};

    LOAD_CHUNK(0, 0);

    uint32_t aRow[2], bRow[4];
#pragma unroll
    for (int mt = 0; mt < 2; mt++)
        aRow[mt] = (uint32_t)((wm * 32 + mt * 16 + (lane & 15)) * 128 + (lane >> 4) * 16);
#pragma unroll
    for (int bp = 0; bp < 4; bp++)
        bRow[bp] = (uint32_t)((wn * 64 + bp * 16 + (lane & 15)) * 128 + (lane >> 4) * 16);

    for (int c = 0; c < NC; c++) {
        if (c + 1 < NC) {
            LOAD_CHUNK(c + 1, (c + 1) & 1);
            CP_WAIT(1);
        } else {
            CP_WAIT(0);
        }
        __syncthreads();
        uint32_t sA = sbase + (uint32_t)(c & 1) * 32768u;
        uint32_t sB = sA + 16384u;
#pragma unroll
        for (int ks = 0; ks < 4; ks++) {
            uint32_t afr[2][4];
#pragma unroll
            for (int mt = 0; mt < 2; mt++)
                LDSM_X4(afr[mt], sA + sw(aRow[mt] + ks * 32));
            uint32_t bfr[4][4];
#pragma unroll
            for (int bp = 0; bp < 4; bp++)
                LDSM_X4(bfr[bp], sB + sw(bRow[bp] + ks * 32));
#pragma unroll
            for (int mt = 0; mt < 2; mt++)
#pragma unroll
                for (int nt = 0; nt < 8; nt++) {
                    uint32_t b0 = bfr[nt >> 1][nt & 1];
                    uint32_t b1 = bfr[nt >> 1][(nt & 1) + 2];
                    mma_f16(acc[mt][nt], afr[mt], b0, b1);
                }
        }
        __syncthreads();
    }

    // ---- epilogue: weighted tanh row reduction ----
    int cb = wn * 64;
    int c0 = 2 * (lane & 3);
    float p[2][2];
#pragma unroll
    for (int mt = 0; mt < 2; mt++)
#pragma unroll
        for (int half = 0; half < 2; half++) {
            float s = 0.f;
#pragma unroll
            for (int nt = 0; nt < 8; nt++) {
#pragma unroll
                for (int j = 0; j < 2; j++) {
                    int n = cb + nt * 8 + c0 + j;
                    s += sv[n] * tanhf(sq[n] + acc[mt][nt][half * 2 + j]);
                }
            }
            p[mt][half] = s;
        }
#pragma unroll
    for (int mt = 0; mt < 2; mt++)
#pragma unroll
        for (int half = 0; half < 2; half++) {
            float s = p[mt][half];
            s += __shfl_xor_sync(0xffffffffu, s, 1);
            s += __shfl_xor_sync(0xffffffffu, s, 2);
            p[mt][half] = s;
        }
    if ((lane & 3) == 0) {
#pragma unroll
        for (int mt = 0; mt < 2; mt++)
#pragma unroll
            for (int half = 0; half < 2; half++)
                sred[wm * 32 + mt * 16 + half * 8 + (lane >> 2)][wn] = p[mt][half];
    }
    __syncthreads();
    if (tid < 128)
        atomicAdd(&g_scores[bm + tid], sred[tid][0] + sred[tid][1]);
}

// ---------------- K3: softmax ----------------
__global__ void k3_softmax(float* __restrict__ out_attn) {
    __shared__ float sm[32];
    int t = threadIdx.x;
    float v[4];
    float mx = -1e30f;
#pragma unroll
    for (int i = 0; i < 4; i++) {
        v[i] = g_scores[t + 1024 * i];
        mx = fmaxf(mx, v[i]);
    }
    mx = warp_max(mx);
    if ((t & 31) == 0) sm[t >> 5] = mx;
    __syncthreads();
    if (t < 32) {
        float m2 = warp_max(sm[t]);
        if (t == 0) sm[0] = m2;
    }
    __syncthreads();
    mx = sm[0];
    __syncthreads();
    float se = 0.f;
#pragma unroll
    for (int i = 0; i < 4; i++) {
        v[i] = expf(v[i] - mx);
        se += v[i];
    }
    se = warp_sum(se);
    if ((t & 31) == 0) sm[t >> 5] = se;
    __syncthreads();
    if (t < 32) {
        float s2 = warp_sum(sm[t]);
        if (t == 0) sm[0] = s2;
    }
    __syncthreads();
    float inv = 1.f / sm[0];
#pragma unroll
    for (int i = 0; i < 4; i++) {
        float a = v[i] * inv;
        g_attn[t + 1024 * i] = a;
        out_attn[t + 1024 * i] = a;
    }
}

// ---------------- K4a: per-block context partials (no atomics) ----------------
__global__ void __launch_bounds__(1024) k4_part(const float* __restrict__ enc) {
    __shared__ float aw[64];
    int t = threadIdx.x;
    int l0 = blockIdx.x * 64;
    if (t < 64) aw[t] = g_attn[l0 + t];
    __syncthreads();
    float s0 = 0.f, s1 = 0.f;
#pragma unroll
    for (int b = 0; b < 8; b++) {
        float e[8];
#pragma unroll
        for (int l = 0; l < 8; l++)
            e[l] = enc[(size_t)(l0 + b * 8 + l) * H + t];
#pragma unroll
        for (int l = 0; l < 8; l++) {
            float w = aw[b * 8 + l];
            if (l & 1) s1 += w * e[l]; else s0 += w * e[l];
        }
    }
    g_cpart[blockIdx.x * H + t] = s0 + s1;
}

// ---------------- K4b: reduce partials ----------------
__global__ void __launch_bounds__(1024) k4_reduce() {
    int t = threadIdx.x;
    float s = 0.f;
#pragma unroll 8
    for (int p = 0; p < 64; p++) s += g_cpart[p * H + t];
    g_context[t] = s;
}

// ---------------- K5: x = relu(cW @ [context;embedded] + cb) ----------------
__global__ void k5_combine(const float* __restrict__ cW, const float* __restrict__ cb,
                           const float* __restrict__ emb, const int* __restrict__ tok) {
    int warp = (blockIdx.x * blockDim.x + threadIdx.x) >> 5;
    int lane = threadIdx.x & 31;
    if (warp >= H) return;
    const float4* r1 = (const float4*)(cW + (size_t)warp * 2 * H);
    const float4* r2 = r1 + H / 4;
    const float4* c4 = (const float4*)g_context;
    const float4* e4 = (const float4*)(emb + (size_t)tok[0] * H);
    float s = 0.f;
#pragma unroll
    for (int i = 0; i < 8; i++) {
        float4 a = r1[lane + 32 * i];
        float4 b = c4[lane + 32 * i];
        s += a.x * b.x + a.y * b.y + a.z * b.z + a.w * b.w;
        float4 a2 = r2[lane + 32 * i];
        float4 b2 = e4[lane + 32 * i];
        s += a2.x * b2.x + a2.y * b2.y + a2.z * b2.z + a2.w * b2.w;
    }
    s = warp_sum(s);
    if (lane == 0) g_x[warp] = fmaxf(s + cb[warp], 0.f);
}

// ---------------- K6: GRU gate GEMVs ----------------
__global__ void k6_gru_gemv(const float* __restrict__ w_ih, const float* __restrict__ b_ih,
                            const float* __restrict__ w_hh, const float* __restrict__ b_hh,
                            const float* __restrict__ hprev) {
    int warp = (blockIdx.x * blockDim.x + threadIdx.x) >> 5;
    int lane = threadIdx.x & 31;
    if (warp >= 6 * H) return;
    const float4* row;
    const float4* vec;
    float bias;
    float* out;
    int idx;
    if (warp < 3 * H) {
        idx = warp;
        row = (const float4*)(w_ih + (size_t)idx * H);
        vec = (const float4*)g_x;
        bias = b_ih[idx];
        out = g_gi;
    } else {
        idx = warp - 3 * H;
        row = (const float4*)(w_hh + (size_t)idx * H);
        vec = (const float4*)hprev;
        bias = b_hh[idx];
        out = g_gh;
    }
    float s = 0.f;
#pragma unroll
    for (int i = 0; i < 8; i++) {
        float4 a = row[lane + 32 * i];
        float4 b = vec[lane + 32 * i];
        s += a.x * b.x + a.y * b.y + a.z * b.z + a.w * b.w;
    }
    s = warp_sum(s);
    if (lane == 0) out[idx] = s + bias;
}

// ---------------- K7: GRU gates + residual ----------------
__global__ void k7_gru(const float* __restrict__ hprev, float* __restrict__ d_out) {
    int i = threadIdx.x;
    float r = 1.f / (1.f + expf(-(g_gi[i] + g_gh[i])));
    float z = 1.f / (1.f + expf(-(g_gi[H + i] + g_gh[H + i])));
    float n = tanhf(g_gi[2 * H + i] + r * g_gh[2 * H + i]);
    float hp = hprev[i];
    float h = (1.f - z) * n + z * hp;
    d_out[V + i] = h;
    g_ov[i] = g_context[i] + h;
}

// ---------------- K8: logits = outW @ ov + outb ----------------
__global__ void __launch_bounds__(256) k8_logits(const float* __restrict__ outW,
                                                 const float* __restrict__ outb,
                                                 float* __restrict__ d_out) {
    __shared__ float4 ov[H / 4];
    int t = threadIdx.x;
    ov[t] = ((const float4*)g_ov)[t];
    __syncthreads();
    int warp = t >> 5, lane = t & 31;
    int v = blockIdx.x * 8 + warp;
    const float4* w4 = (const float4*)(outW + (size_t)v * H);
    float s = 0.f;
#pragma unroll
    for (int i = 0; i < 8; i++) {
        float4 a = w4[lane + 32 * i];
        float4 b = ov[lane + 32 * i];
        s += a.x * b.x + a.y * b.y + a.z * b.z + a.w * b.w;
    }
    s = warp_sum(s);
    if (lane == 0) d_out[v] = s + outb[v];
}

// ---------------- launch ----------------
extern "C" void kernel_launch(void* const* d_in, const int* in_sizes, int n_in,
                              void* d_out, int out_size) {
    const int* tok = (const int*)d_in[0];
    const float* hidden = (const float*)d_in[1];
    const float* enc = (const float*)d_in[2];
    const float* emb = (const float*)d_in[3];
    const float* wW = (const float*)d_in[4];
    const float* wb = (const float*)d_in[5];
    const float* uW = (const float*)d_in[6];
    const float* ub = (const float*)d_in[7];
    const float* vW = (const float*)d_in[8];
    const float* cW = (const float*)d_in[9];
    const float* cb = (const float*)d_in[10];
    const float* w_ih = (const float*)d_in[11];
    const float* b_ih = (const float*)d_in[12];
    const float* w_hh = (const float*)d_in[13];
    const float* b_hh = (const float*)d_in[14];
    const float* outW = (const float*)d_in[15];
    const float* outb = (const float*)d_in[16];
    float* out = (float*)d_out;

    cudaFuncSetAttribute(k2_scores, cudaFuncAttributeMaxDynamicSharedMemorySize, SMEM_DYN);

    k_prologue<<<L + H + 128, 256>>>(enc, uW, hidden, wW, wb, ub);
    k2_scores<<<dim3(L / 128, H / 128), 256, SMEM_DYN>>>(vW);
    k3_softmax<<<1, 1024>>>(out + V + H);
    k4_part<<<64, 1024>>>(enc);
    k4_reduce<<<1, 1024>>>();
    k5_combine<<<128, 256>>>(cW, cb, emb, tok);
    k6_gru_gemv<<<(6 * H) / 8, 256>>>(w_ih, b_ih, w_hh, b_hh, hidden);
    k7_gru<<<1, 1024>>>(hidden, out);
    k8_logits<<<V / 8, 256>>>(outW, outb, out);
}